// round 15
// baseline (speedup 1.0000x reference)
#include <cuda_runtime.h>
#include <cuda_fp16.h>
#include <math.h>
#include <stdint.h>

// ---------------------------------------------------------------------------
// BLSTM: B=128, S=512, H=1024, VOCAB=128
// fp16 HMMA recurrence (fp32 acc), per-k128-chunk producer flags with
// red.release publish + tid0 fast-path checks, progressive chunk schedule,
// W chunk-0 pre-staged. 2-product HMMA output projection.
// ---------------------------------------------------------------------------

#define Bsz   128
#define Ssz   512
#define Hsz   1024
#define Vsz   128
#define G4    4096
#define KT    32
#define NB    128
#define NBD   64        // CTAs per direction

#define SC_W  2048.0f
#define SC_WI (1.0f/2048.0f)

// recurrence: sub-block = A 16K + W 8K = 24 KB; buffer = 4 sub-blocks = 96 KB
#define SUBB      24576
#define RBUF_R    (4 * SUBB)
#define SMEM_REC  (2 * RBUF_R)
// projection buffer: A 32K | Wh 16K | Wl 16K = 64 KB ; double = 128 KB
#define RBUF_P    65536
#define SMEM_PROJ (2 * RBUF_P)

typedef unsigned long long u64;
typedef unsigned int u32;

// ------------------------- device scratch -----------------------------------
__device__ float  g_token_gates[2][Vsz][G4];       // LUT original order
__device__ float  g_lutP[2][Vsz][G4];              // LUT permuted (nP)
__device__ __half g_h16[2][Bsz][Hsz];              // initial h only
__device__ __half g_Wh[2][G4][Hsz];                // W^T fp16 (permuted nP)
__device__ __half g_out16[2][Ssz][Bsz][Hsz];       // h history fp16 (= exchange)
__device__ __half g_WoTh[Vsz][2 * Hsz];            // W_out^T hi
__device__ __half g_WoTl[Vsz][2 * Hsz];            // W_out^T lo * SC_W
__device__ float  g_hfin[2][Bsz][Hsz];
__device__ float  g_cfin[2][Bsz][Hsz];
__device__ __align__(128) u32 g_flag[2][8];        // per-dir per-k128 chunk flags
__device__ volatile unsigned g_gen2[2];
__device__ unsigned g_count2[2];

// ------------------------- helpers ------------------------------------------
static __device__ __forceinline__ uint32_t smem_u32(const void* p) {
    uint32_t a;
    asm("{ .reg .u64 t; cvta.to.shared.u64 t, %1; cvt.u32.u64 %0, t; }"
        : "=r"(a) : "l"(p));
    return a;
}
static __device__ __forceinline__ uint32_t swz(uint32_t o) {
    return o ^ ((o >> 3) & 0x70);
}
#define CPA(dst, src) \
    asm volatile("cp.async.cg.shared.global [%0], [%1], 16;" \
                 :: "r"(dst), "l"(src) : "memory")

static __device__ __forceinline__ void ldsm4(u32 r[4], u32 addr) {
    asm volatile("ldmatrix.sync.aligned.m8n8.x4.shared.b16 {%0,%1,%2,%3}, [%4];"
                 : "=r"(r[0]), "=r"(r[1]), "=r"(r[2]), "=r"(r[3]) : "r"(addr));
}
static __device__ __forceinline__ void mma_f16(float d[4], const u32 a[4],
                                               u32 b0, u32 b1) {
    asm volatile(
        "mma.sync.aligned.m16n8k16.row.col.f32.f16.f16.f32 "
        "{%0,%1,%2,%3}, {%4,%5,%6,%7}, {%8,%9}, {%0,%1,%2,%3};"
        : "+f"(d[0]), "+f"(d[1]), "+f"(d[2]), "+f"(d[3])
        : "r"(a[0]), "r"(a[1]), "r"(a[2]), "r"(a[3]), "r"(b0), "r"(b1));
}
static __device__ __forceinline__ u32 ldacq(const u32* p) {
    u32 v;
    asm volatile("ld.acquire.gpu.global.u32 %0, [%1];" : "=r"(v) : "l"(p) : "memory");
    return v;
}
static __device__ __forceinline__ float tanh_fast(float v) {
    return 1.f - 2.f / (1.f + __expf(2.f * v));
}
static __device__ __forceinline__ float sigmoid_fast(float v) {
    return 1.f / (1.f + __expf(-v));
}

// ------------------------- per-direction barrier (end-of-kernel only) --------
__device__ __forceinline__ void grid_barrier_dir(int dir)
{
    __syncthreads();
    if (threadIdx.x == 0) {
        unsigned gen = g_gen2[dir];
        __threadfence();
        unsigned t = atomicAdd(&g_count2[dir], 1);
        if (t == NBD - 1) {
            g_count2[dir] = 0;
            __threadfence();
            g_gen2[dir] = gen + 1;
        } else {
            while (g_gen2[dir] == gen) {}
        }
        __threadfence();
    }
    __syncthreads();
}

// ------------------------- FFMA GEMM core (lut only) -------------------------
__device__ __forceinline__ void gemm_tile_K(
    const float* __restrict__ A, int lda,
    const float* __restrict__ B, int ldb,
    int K, u64 acc[8][4],
    float* As, float* Bs)
{
    const int tid = threadIdx.x;
    const int tx  = tid & 15;
    const int ty  = tid >> 4;

    float4 ra[4], rb[4];
#pragma unroll
    for (int i = 0; i < 4; i++) {
        int c = tid + 256 * i;
        ra[i] = *(const float4*)(A + (size_t)(c >> 3) * lda + ((c & 7) << 2));
        rb[i] = *(const float4*)(B + (size_t)(c >> 5) * ldb + ((c & 31) << 2));
    }
    for (int k0 = 0; k0 < K; k0 += KT) {
        __syncthreads();
#pragma unroll
        for (int i = 0; i < 4; i++) {
            int c = tid + 256 * i;
            *(float4*)(As + (c >> 3) * KT  + ((c & 7)  << 2)) = ra[i];
            *(float4*)(Bs + (c >> 5) * 128 + ((c & 31) << 2)) = rb[i];
        }
        __syncthreads();
        const int k1 = k0 + KT;
        if (k1 < K) {
#pragma unroll
            for (int i = 0; i < 4; i++) {
                int c = tid + 256 * i;
                ra[i] = *(const float4*)(A + (size_t)(c >> 3) * lda + k1 + ((c & 7) << 2));
                rb[i] = *(const float4*)(B + (size_t)(k1 + (c >> 5)) * ldb + ((c & 31) << 2));
            }
        }
#pragma unroll
        for (int k = 0; k < KT; k++) {
            const float* brow = Bs + k * 128 + tx * 8;
            ulonglong2 q0 = *(const ulonglong2*)brow;
            ulonglong2 q1 = *(const ulonglong2*)(brow + 4);
            u64 bp0 = q0.x, bp1 = q0.y, bp2 = q1.x, bp3 = q1.y;
#pragma unroll
            for (int i = 0; i < 8; i++) {
                float a = As[(ty * 8 + i) * KT + k];
                u64 ad;
                asm("mov.b64 %0, {%1, %1};" : "=l"(ad) : "f"(a));
                asm("fma.rn.f32x2 %0, %1, %2, %0;" : "+l"(acc[i][0]) : "l"(ad), "l"(bp0));
                asm("fma.rn.f32x2 %0, %1, %2, %0;" : "+l"(acc[i][1]) : "l"(ad), "l"(bp1));
                asm("fma.rn.f32x2 %0, %1, %2, %0;" : "+l"(acc[i][2]) : "l"(ad), "l"(bp2));
                asm("fma.rn.f32x2 %0, %1, %2, %0;" : "+l"(acc[i][3]) : "l"(ad), "l"(bp3));
            }
        }
    }
}
union F4U { u64 u[2]; float4 v; };

// ------------------------- prep kernels --------------------------------------
__global__ void k_hinit(const float* __restrict__ h_f, const float* __restrict__ h_b)
{
    int i = blockIdx.x * blockDim.x + threadIdx.x;
    if (i < 2 * Bsz * Hsz) {
        int dir = i >> 17, b = (i >> 10) & 127, k = i & 1023;
        g_h16[dir][b][k] = __float2half((dir ? h_b : h_f)[b * Hsz + k]);
    }
}

// nP = slice*64 + jh*32 + g*8 + jl3  <->  orig col = g*1024 + slice*16 + jh*8 + jl3
__global__ void __launch_bounds__(256) k_wprep(const float* __restrict__ W_f,
                                               const float* __restrict__ W_b)
{
    int bid   = blockIdx.x;                 // 8192 blocks
    int kblk  = bid & 15;
    int g     = (bid >> 4) & 3;
    int slice = (bid >> 6) & 63;
    int dir   = bid >> 12;
    const float* W = dir ? W_b : W_f;

    int jl = threadIdx.x >> 4;              // 0..15
    int kk = threadIdx.x & 15;
    int col = g * 1024 + slice * 16 + jl;
    int jh = jl >> 3, jl3 = jl & 7;
    int nP  = slice * 64 + jh * 32 + g * 8 + jl3;
#pragma unroll
    for (int r = 0; r < 4; r++) {
        int k = kblk * 64 + kk + r * 16;
        g_Wh[dir][nP][k] = __float2half(W[(size_t)(Hsz + k) * G4 + col]);
    }
}

__global__ void k_lutperm()
{
    int i = blockIdx.x * blockDim.x + threadIdx.x;
    if (i < 2 * Vsz * G4) {
        int d = i >> 19, v = (i >> 12) & 127, nP = i & 4095;
        int slice = nP >> 6, rem = nP & 63;
        int jh = rem >> 5, g = (rem >> 3) & 3, jl3 = rem & 7;
        g_lutP[d][v][nP] =
            g_token_gates[d][v][g * 1024 + slice * 16 + jh * 8 + jl3];
    }
}

__global__ void k_woutprep(const float* __restrict__ W_out)
{
    int i = blockIdx.x * blockDim.x + threadIdx.x;
    if (i < Vsz * 2 * Hsz) {
        int v = i >> 11, k = i & 2047;
        float wv = W_out[(size_t)k * Vsz + v];
        __half hi = __float2half(wv);
        g_WoTh[v][k] = hi;
        g_WoTl[v][k] = __float2half((wv - __half2float(hi)) * SC_W);
    }
}

__global__ void __launch_bounds__(256) k_lut(
    const float* __restrict__ emb,
    const float* __restrict__ W_f, const float* __restrict__ b_f,
    const float* __restrict__ W_b, const float* __restrict__ b_b)
{
    __shared__ __align__(16) float As[128 * KT];
    __shared__ __align__(16) float Bs[KT * 128];
    int dir   = blockIdx.x >> 5;
    int slice = blockIdx.x & 31;
    const float* W    = dir ? W_b : W_f;
    const float* bias = dir ? b_b : b_f;

    u64 acc[8][4] = {};
    gemm_tile_K(emb, Hsz, W + slice * 128, G4, Hsz, acc, As, Bs);

    const int tx = threadIdx.x & 15, ty = threadIdx.x >> 4;
    float* C = &g_token_gates[dir][0][0] + slice * 128;
    float4 bv0 = *(const float4*)(bias + slice * 128 + tx * 8);
    float4 bv1 = *(const float4*)(bias + slice * 128 + tx * 8 + 4);
#pragma unroll
    for (int i = 0; i < 8; i++) {
        int r = ty * 8 + i;
        F4U u0; u0.u[0] = acc[i][0]; u0.u[1] = acc[i][1];
        F4U u1; u1.u[0] = acc[i][2]; u1.u[1] = acc[i][3];
        u0.v.x += bv0.x; u0.v.y += bv0.y; u0.v.z += bv0.z; u0.v.w += bv0.w;
        u1.v.x += bv1.x; u1.v.y += bv1.y; u1.v.z += bv1.z; u1.v.w += bv1.w;
        *(float4*)(C + (size_t)r * G4 + tx * 8)     = u0.v;
        *(float4*)(C + (size_t)r * G4 + tx * 8 + 4) = u1.v;
    }
}

// ------------------------- recurrence staging (k64 sub-blocks) ---------------
// sub-block layout: [0,16K) A 128 rows x 128B swz ; [16K,24K) W 64 rows x 128B
__device__ __forceinline__ void issue_subA(uint32_t sub, const char* pA,
                                           size_t koffB, int tid)
{
#pragma unroll
    for (int i = 0; i < 4; i++) {
        int idx = tid + 256 * i;
        int r = idx >> 3, seg = idx & 7;
        CPA(sub + swz(r * 128 + seg * 16),
            pA + (size_t)r * 2048 + koffB + seg * 16);
    }
}
__device__ __forceinline__ void issue_subW(uint32_t sub, const char* pWh,
                                           size_t koffB, int tid)
{
#pragma unroll
    for (int i = 0; i < 2; i++) {
        int idx = tid + 256 * i;
        int r = (idx >> 3) & 63, seg = idx & 7;
        CPA(sub + 16384 + swz(r * 128 + seg * 16),
            pWh + (size_t)r * 2048 + koffB + seg * 16);
    }
}
// issue all sub-blocks of chunk c into buffer buf
__device__ __forceinline__ void issue_chunk(uint32_t buf, const char* pA,
    const char* pWh, int cum, int nkc, int tid)
{
#pragma unroll
    for (int b2 = 0; b2 < 4; b2++) {
        if (b2 < nkc) {
            const size_t koffB = (size_t)(cum + b2) * 128;
            issue_subA(buf + b2 * SUBB, pA, koffB, tid);
            issue_subW(buf + b2 * SUBB, pWh, koffB, tid);
        }
    }
    asm volatile("cp.async.commit_group;" ::: "memory");
}

// k64 sub-block math (fp32 acc, warp layout 4 mrow x 2 ncol)
#define SUB_MATH(sub)                                                           \
    _Pragma("unroll")                                                           \
    for (int kk = 0; kk < 4; kk++) {                                            \
        const uint32_t koff = kk * 32 + lh * 16;                                \
        u32 ah0[4], ah1[4];                                                     \
        ldsm4(ah0, (sub) + swz((mrow * 32 + lr) * 128 + koff));                 \
        ldsm4(ah1, (sub) + swz((mrow * 32 + 16 + lr) * 128 + koff));            \
        const uint32_t wb2 = (sub) + 16384;                                     \
        _Pragma("unroll")                                                       \
        for (int nh = 0; nh < 2; nh++) {                                        \
            u32 wh[4];                                                          \
            uint32_t wro = swz((ncol * 32 + nh * 16 + lr) * 128 + koff);        \
            ldsm4(wh, wb2 + wro);                                               \
            mma_f16(d1[nh * 2],     ah0, wh[0], wh[2]);                         \
            mma_f16(d1[nh * 2 + 1], ah0, wh[1], wh[3]);                         \
            mma_f16(d1[4 + nh * 2],     ah1, wh[0], wh[2]);                     \
            mma_f16(d1[4 + nh * 2 + 1], ah1, wh[1], wh[3]);                     \
        }                                                                       \
    }

#define CHUNK_MATH(c, cbuf)                                                     \
    _Pragma("unroll")                                                           \
    for (int b2 = 0; b2 < 4; b2++) {                                            \
        if (b2 < NKC[c]) { const uint32_t sub = (cbuf) + b2 * SUBB; SUB_MATH(sub) } \
    }

// ------------------------- persistent recurrence -----------------------------
// chunk schedule (k64 units): sizes {1,1,2,4,4,4}, offsets {0,1,2,4,8,12}
// flags per k128 chunk; chunk c needs flags FLO[c]..FHI[c]
__global__ void __launch_bounds__(256, 1) k_recurrent(
    const int* __restrict__ x,
    const float* __restrict__ c_f, const float* __restrict__ c_b)
{
    extern __shared__ __align__(128) char dsm[];
    __shared__ int sready;
    const uint32_t sb = smem_u32(dsm);

    const int tid  = threadIdx.x;
    const int w    = tid >> 5, lane = tid & 31;
    const int lr   = lane & 15, lh = lane >> 4;
    const int q    = lane & 3,  r0 = lane >> 2;
    const int blk  = blockIdx.x;
    const int dir  = blk >> 6, slice = blk & 63;
    const int n0   = slice * 64, j0 = slice * 16;
    const int mrow = w >> 1, ncol = w & 1;

    const int NKC[6] = {1, 1, 2, 4, 4, 4};
    const int CUM[6] = {0, 1, 2, 4, 8, 12};
    const int FLO[6] = {0, 0, 1, 2, 4, 6};
    const int FHI[6] = {0, 0, 1, 3, 5, 7};

    float c_reg[8];
    {
        const float* cin = dir ? c_b : c_f;
#pragma unroll
        for (int ci = 0; ci < 8; ci++) {
            int mt = ci >> 2, rr = (ci >> 1) & 1, jj = ci & 1;
            int b  = mrow * 32 + mt * 16 + rr * 8 + r0;
            int jl = ncol * 8 + 2 * q + jj;
            c_reg[ci] = cin[(size_t)b * Hsz + j0 + jl];
        }
    }

    const char* pWh = (const char*)&g_Wh[dir][n0][0];
    u32* flags = &g_flag[dir][0];

    // pre-stage W of chunk 0 (k64, h-independent) into buffer 0
    issue_subW(sb, pWh, 0, tid);
    asm volatile("cp.async.commit_group;" ::: "memory");

    for (int s = 0; s < Ssz; s++) {
        const int ts = dir ? (Ssz - 1 - s) : s;
        const char* pA = (s == 0)
            ? (const char*)&g_h16[dir][0][0]
            : (const char*)&g_out16[dir][dir ? (Ssz - s) : (s - 1)][0][0];
        const u32 tgt = (u32)(8 * s);    // each flag reaches 8*s when h(s) ready

        // gate chunk 0 on its 8 producers only
        if (s > 0) {
            if (tid == 0) { while (ldacq(&flags[0]) < tgt) {} }
            __syncthreads();
        }
        issue_subA(sb, pA, 0, tid);
        asm volatile("cp.async.commit_group;" ::: "memory");

        // LUT prefetch (hides L2 latency under the GEMM)
        float2 lp[2][2][4];
#pragma unroll
        for (int mt = 0; mt < 2; mt++)
#pragma unroll
            for (int rr = 0; rr < 2; rr++) {
                const int b = mrow * 32 + mt * 16 + rr * 8 + r0;
                const int tok = __ldg(&x[b * Ssz + ts]);
                const float* lutb = &g_lutP[dir][tok][n0 + ncol * 32];
#pragma unroll
                for (int g = 0; g < 4; g++)
                    lp[mt][rr][g] = *(const float2*)(lutb + g * 8 + 2 * q);
            }

        float d1[8][4];
#pragma unroll
        for (int i = 0; i < 8; i++)
#pragma unroll
            for (int r = 0; r < 4; r++) d1[i][r] = 0.f;

#pragma unroll
        for (int c = 0; c < 6; c++) {
            asm volatile("cp.async.wait_group 0;" ::: "memory");
            // fast-path check for chunk c+1's producer flags (tid0, non-blocking)
            if (c < 5 && tid == 0) {
                int ok = (ldacq(&flags[FLO[c + 1]]) >= tgt);
                if (ok && FHI[c + 1] != FLO[c + 1])
                    ok = (ldacq(&flags[FHI[c + 1]]) >= tgt);
                sready = ok;
            }
            __syncthreads();
            if (c < 5) {
                const uint32_t nbuf = sb + ((c + 1) & 1) * RBUF_R;
                const uint32_t cbuf = sb + (c & 1) * RBUF_R;
                if (sready) {
                    issue_chunk(nbuf, pA, pWh, CUM[c + 1], NKC[c + 1], tid);
                    CHUNK_MATH(c, cbuf)
                } else {
                    CHUNK_MATH(c, cbuf)
                    if (tid == 0) {
                        while (ldacq(&flags[FLO[c + 1]]) < tgt) {}
                        if (FHI[c + 1] != FLO[c + 1])
                            while (ldacq(&flags[FHI[c + 1]]) < tgt) {}
                    }
                    __syncthreads();
                    issue_chunk(nbuf, pA, pWh, CUM[c + 1], NKC[c + 1], tid);
                }
            } else {
                const uint32_t cbuf = sb + (c & 1) * RBUF_R;
                CHUNK_MATH(c, cbuf)
            }
        }

        // pre-stage next step's W chunk 0 into buffer 0 (free after chunk-4
        // math; chunk 5 ran from buffer 1). Hidden behind epilogue + wait.
        if (s < Ssz - 1) {
            issue_subW(sb, pWh, 0, tid);
            asm volatile("cp.async.commit_group;" ::: "memory");
        }

        // ---- epilogue: thread-local LSTM update; publish h(s+1) ----
#pragma unroll
        for (int mt = 0; mt < 2; mt++) {
#pragma unroll
            for (int rr = 0; rr < 2; rr++) {
                const int b = mrow * 32 + mt * 16 + rr * 8 + r0;
                float hv[2];
#pragma unroll
                for (int jj = 0; jj < 2; jj++) {
                    const int ri = rr * 2 + jj;
                    float zi = d1[mt*4+0][ri] + (jj ? lp[mt][rr][0].y : lp[mt][rr][0].x);
                    float zf = d1[mt*4+1][ri] + (jj ? lp[mt][rr][1].y : lp[mt][rr][1].x);
                    float zo = d1[mt*4+2][ri] + (jj ? lp[mt][rr][2].y : lp[mt][rr][2].x);
                    float zg = d1[mt*4+3][ri] + (jj ? lp[mt][rr][3].y : lp[mt][rr][3].x);
                    float ig = sigmoid_fast(zi);
                    float fg = sigmoid_fast(zf);
                    float og = sigmoid_fast(zo);
                    const int ci = mt * 4 + rr * 2 + jj;
                    float cc = fg * c_reg[ci] + ig * tanh_fast(zg);
                    c_reg[ci] = cc;
                    hv[jj] = og * tanh_fast(cc);
                }
                __half2 hp = __floats2half2_rn(hv[0], hv[1]);
                const int jcol = j0 + ncol * 8 + 2 * q;
                *(u32*)(&g_out16[dir][ts][b][jcol]) = *(u32*)&hp;
                if (s == Ssz - 1)
                    *(float2*)(&g_hfin[dir][b][jcol]) = make_float2(hv[0], hv[1]);
            }
        }

        // publish with release semantics (orders the h stores)
        __syncthreads();
        if (tid == 0)
            asm volatile("red.release.gpu.global.add.u32 [%0], %1;"
                         :: "l"(&flags[slice >> 3]), "r"(1u) : "memory");
    }

    // final c writeback
#pragma unroll
    for (int ci = 0; ci < 8; ci++) {
        int mt = ci >> 2, rr = (ci >> 1) & 1, jj = ci & 1;
        int b  = mrow * 32 + mt * 16 + rr * 8 + r0;
        int jl = ncol * 8 + 2 * q + jj;
        g_cfin[dir][b][j0 + jl] = c_reg[ci];
    }

    // reset flags for the next graph replay (after all CTAs stop polling)
    grid_barrier_dir(dir);
    if (slice == 0 && tid == 0) {
#pragma unroll
        for (int i2 = 0; i2 < 8; i2++) flags[i2] = 0;
    }
}

// ------------------------- HMMA output projection -----------------------------
__device__ __forceinline__ void proj_issue(uint32_t buf, int t,
    const char* pW0, const char* pW1, int kc, int tid)
{
    const int dirc = kc >> 3;
    const char* pA = (const char*)&g_out16[dirc][t][0][0];
    const size_t kb = (size_t)(kc & 7) * 256;
#pragma unroll
    for (int i = 0; i < 8; i++) {
        int idx = tid + 256 * i;
        int kh = idx >> 10, r = (idx >> 3) & 127, seg = idx & 7;
        CPA(buf + kh * 16384 + swz(r * 128 + seg * 16),
            pA + (size_t)r * 2048 + kb + kh * 128 + seg * 16);
    }
    const size_t kbw = (size_t)kc * 256;
#pragma unroll
    for (int i = 0; i < 4; i++) {
        int idx = tid + 256 * i;
        int kh = idx >> 9, r = (idx >> 3) & 63, seg = idx & 7;
        uint32_t so = kh * 8192 + swz(r * 128 + seg * 16);
        size_t go = (size_t)r * 4096 + kbw + kh * 128 + seg * 16;
        CPA(buf + 32768 + so, pW0 + go);
        CPA(buf + 49152 + so, pW1 + go);
    }
    asm volatile("cp.async.commit_group;" ::: "memory");
}

#define CHUNK_MATH_2P(base)                                                     \
    _Pragma("unroll")                                                           \
    for (int kk = 0; kk < 8; kk++) {                                            \
        const int kh = kk >> 2;                                                 \
        const uint32_t koff = (kk & 3) * 32 + lh * 16;                          \
        const uint32_t ab = (base) + kh * 16384;                                \
        u32 ah0[4], ah1[4];                                                     \
        ldsm4(ah0, ab + swz((mrow * 32 + lr) * 128 + koff));                    \
        ldsm4(ah1, ab + swz((mrow * 32 + 16 + lr) * 128 + koff));               \
        const uint32_t wb = (base) + 32768 + kh * 8192;                         \
        _Pragma("unroll")                                                       \
        for (int nh = 0; nh < 2; nh++) {                                        \
            u32 wh[4], wl[4];                                                   \
            uint32_t wro = swz((ncol * 32 + nh * 16 + lr) * 128 + koff);        \
            ldsm4(wh, wb + wro);                                                \
            ldsm4(wl, wb + 16384 + wro);                                        \
            mma_f16(d1[nh * 2],     ah0, wh[0], wh[2]);                         \
            mma_f16(d1[nh * 2 + 1], ah0, wh[1], wh[3]);                         \
            mma_f16(d2[nh * 2],     ah0, wl[0], wl[2]);                         \
            mma_f16(d2[nh * 2 + 1], ah0, wl[1], wl[3]);                         \
            mma_f16(d1[4 + nh * 2],     ah1, wh[0], wh[2]);                     \
            mma_f16(d1[4 + nh * 2 + 1], ah1, wh[1], wh[3]);                     \
            mma_f16(d2[4 + nh * 2],     ah1, wl[0], wl[2]);                     \
            mma_f16(d2[4 + nh * 2 + 1], ah1, wl[1], wl[3]);                     \
        }                                                                       \
    }

__global__ void __launch_bounds__(256, 1) k_proj_h(
    const float* __restrict__ b_out, float* __restrict__ out)
{
    extern __shared__ __align__(128) char dsm[];
    const uint32_t sb = smem_u32(dsm);

    const int tid  = threadIdx.x;
    const int w    = tid >> 5, lane = tid & 31;
    const int lr   = lane & 15, lh = lane >> 4;
    const int q    = lane & 3,  r0 = lane >> 2;
    const int bid  = blockIdx.x;          // 1024
    const int t    = bid >> 1, vh = bid & 1;
    const int mrow = w >> 1, ncol = w & 1;

    const char* pW0 = (const char*)&g_WoTh[vh * 64][0];
    const char* pW1 = (const char*)&g_WoTl[vh * 64][0];

    float d1[8][4] = {}, d2[8][4] = {};
    proj_issue(sb, t, pW0, pW1, 0, tid);

    for (int kc = 0; kc < 16; kc++) {
        asm volatile("cp.async.wait_group 0;" ::: "memory");
        __syncthreads();
        if (kc < 15)
            proj_issue(sb + ((kc + 1) & 1) * RBUF_P, t, pW0, pW1, kc + 1, tid);
        const uint32_t base = sb + (kc & 1) * RBUF_P;
        CHUNK_MATH_2P(base)
    }

#pragma unroll
    for (int mt = 0; mt < 2; mt++) {
#pragma unroll
        for (int rr = 0; rr < 2; rr++) {
            const int b = mrow * 32 + mt * 16 + rr * 8 + r0;
#pragma unroll
            for (int nt = 0; nt < 4; nt++) {
                const int v = vh * 64 + ncol * 32 + nt * 8 + 2 * q;
                float2 bv = *(const float2*)(b_out + v);
                float2 o;
                o.x = d1[mt*4+nt][rr*2+0] + d2[mt*4+nt][rr*2+0] * SC_WI + bv.x;
                o.y = d1[mt*4+nt][rr*2+1] + d2[mt*4+nt][rr*2+1] * SC_WI + bv.y;
                *(float2*)(out + ((size_t)b * Ssz + t) * Vsz + v) = o;
            }
        }
    }
}

// ------------------------- final state writeback ------------------------------
__global__ void k_states(float* __restrict__ out)
{
    int i = blockIdx.x * blockDim.x + threadIdx.x;
    if (i < Bsz * Hsz) {
        int b = i >> 10, j = i & 1023;
        size_t base = (size_t)Bsz * Ssz * Vsz;
        out[base + 0 * Bsz * Hsz + i] = g_hfin[0][b][j];
        out[base + 1 * Bsz * Hsz + i] = g_hfin[1][b][j];
        out[base + 2 * Bsz * Hsz + i] = g_cfin[0][b][j];
        out[base + 3 * Bsz * Hsz + i] = g_cfin[1][b][j];
    }
}

// ---------------------------------------------------------------------------
extern "C" void kernel_launch(void* const* d_in, const int* in_sizes, int n_in,
                              void* d_out, int out_size)
{
    const int*   x     = (const int*)  d_in[0];
    const float* h_f   = (const float*)d_in[1];
    const float* h_b   = (const float*)d_in[2];
    const float* c_f   = (const float*)d_in[3];
    const float* c_b   = (const float*)d_in[4];
    const float* emb   = (const float*)d_in[5];
    const float* W_f   = (const float*)d_in[6];
    const float* b_f   = (const float*)d_in[7];
    const float* W_b   = (const float*)d_in[8];
    const float* b_b   = (const float*)d_in[9];
    const float* W_out = (const float*)d_in[10];
    const float* b_out = (const float*)d_in[11];
    float* out = (float*)d_out;

    static bool attr_done = false;
    if (!attr_done) {
        cudaFuncSetAttribute(k_recurrent,
                             cudaFuncAttributeMaxDynamicSharedMemorySize, SMEM_REC);
        cudaFuncSetAttribute(k_proj_h,
                             cudaFuncAttributeMaxDynamicSharedMemorySize, SMEM_PROJ);
        attr_done = true;
    }

    k_hinit<<<1024, 256>>>(h_f, h_b);
    k_wprep<<<8192, 256>>>(W_f, W_b);
    k_lut<<<64, 256>>>(emb, W_f, b_f, W_b, b_b);
    k_lutperm<<<4096, 256>>>();
    k_woutprep<<<1024, 256>>>(W_out);

    k_recurrent<<<NB, 256, SMEM_REC>>>(x, c_f, c_b);

    k_proj_h<<<1024, 256, SMEM_PROJ>>>(b_out, out);
    if (out_size >= (int)((size_t)Bsz * Ssz * Vsz + 4 * Bsz * Hsz))
        k_states<<<512, 256>>>(out);
}

// round 16
// speedup vs baseline: 1.1666x; 1.1666x over previous
#include <cuda_runtime.h>
#include <cuda_fp16.h>
#include <math.h>
#include <stdint.h>

// ---------------------------------------------------------------------------
// BLSTM: B=128, S=512, H=1024, VOCAB=128
// fp16 HMMA recurrence (fp32 acc), one-sided per-direction counter with
// red.release publish, progressive chunk schedule (k64,k64,k128,k256x3),
// W chunk-0 pre-staged after publish. 1-product HMMA output projection.
// ---------------------------------------------------------------------------

#define Bsz   128
#define Ssz   512
#define Hsz   1024
#define Vsz   128
#define G4    4096
#define KT    32
#define NB    128
#define NBD   64        // CTAs per direction

// recurrence: sub-block = A 16K + W 8K = 24 KB; buffer = 4 sub-blocks = 96 KB
#define SUBB      24576
#define RBUF_R    (4 * SUBB)
#define SMEM_REC  (2 * RBUF_R)
// projection buffer: A 32K | Wh 16K = 48 KB ; double = 96 KB
#define RBUF_P    49152
#define SMEM_PROJ (2 * RBUF_P)

typedef unsigned long long u64;
typedef unsigned int u32;

// ------------------------- device scratch -----------------------------------
__device__ float  g_token_gates[2][Vsz][G4];       // LUT original order
__device__ float  g_lutP[2][Vsz][G4];              // LUT permuted (nP)
__device__ __half g_h16[2][Bsz][Hsz];              // initial h only
__device__ __half g_Wh[2][G4][Hsz];                // W^T fp16 (permuted nP)
__device__ __half g_out16[2][Ssz][Bsz][Hsz];       // h history fp16 (= exchange)
__device__ __half g_WoTh[Vsz][2 * Hsz];            // W_out^T fp16
__device__ float  g_hfin[2][Bsz][Hsz];
__device__ float  g_cfin[2][Bsz][Hsz];
__device__ u32    g_cnt[2];                        // per-dir step-completion count
__device__ volatile unsigned g_gen2[2];
__device__ unsigned g_count2[2];

// ------------------------- helpers ------------------------------------------
static __device__ __forceinline__ uint32_t smem_u32(const void* p) {
    uint32_t a;
    asm("{ .reg .u64 t; cvta.to.shared.u64 t, %1; cvt.u32.u64 %0, t; }"
        : "=r"(a) : "l"(p));
    return a;
}
static __device__ __forceinline__ uint32_t swz(uint32_t o) {
    return o ^ ((o >> 3) & 0x70);
}
#define CPA(dst, src) \
    asm volatile("cp.async.cg.shared.global [%0], [%1], 16;" \
                 :: "r"(dst), "l"(src) : "memory")

static __device__ __forceinline__ void ldsm4(u32 r[4], u32 addr) {
    asm volatile("ldmatrix.sync.aligned.m8n8.x4.shared.b16 {%0,%1,%2,%3}, [%4];"
                 : "=r"(r[0]), "=r"(r[1]), "=r"(r[2]), "=r"(r[3]) : "r"(addr));
}
static __device__ __forceinline__ void mma_f16(float d[4], const u32 a[4],
                                               u32 b0, u32 b1) {
    asm volatile(
        "mma.sync.aligned.m16n8k16.row.col.f32.f16.f16.f32 "
        "{%0,%1,%2,%3}, {%4,%5,%6,%7}, {%8,%9}, {%0,%1,%2,%3};"
        : "+f"(d[0]), "+f"(d[1]), "+f"(d[2]), "+f"(d[3])
        : "r"(a[0]), "r"(a[1]), "r"(a[2]), "r"(a[3]), "r"(b0), "r"(b1));
}
static __device__ __forceinline__ float tanh_fast(float v) {
    return 1.f - 2.f / (1.f + __expf(2.f * v));
}
static __device__ __forceinline__ float sigmoid_fast(float v) {
    return 1.f / (1.f + __expf(-v));
}

// ------------------------- per-direction barrier (end-of-kernel only) --------
__device__ __forceinline__ void grid_barrier_dir(int dir)
{
    __syncthreads();
    if (threadIdx.x == 0) {
        unsigned gen = g_gen2[dir];
        __threadfence();
        unsigned t = atomicAdd(&g_count2[dir], 1);
        if (t == NBD - 1) {
            g_count2[dir] = 0;
            __threadfence();
            g_gen2[dir] = gen + 1;
        } else {
            while (g_gen2[dir] == gen) {}
        }
        __threadfence();
    }
    __syncthreads();
}

// ------------------------- FFMA GEMM core (lut only) -------------------------
__device__ __forceinline__ void gemm_tile_K(
    const float* __restrict__ A, int lda,
    const float* __restrict__ B, int ldb,
    int K, u64 acc[8][4],
    float* As, float* Bs)
{
    const int tid = threadIdx.x;
    const int tx  = tid & 15;
    const int ty  = tid >> 4;

    float4 ra[4], rb[4];
#pragma unroll
    for (int i = 0; i < 4; i++) {
        int c = tid + 256 * i;
        ra[i] = *(const float4*)(A + (size_t)(c >> 3) * lda + ((c & 7) << 2));
        rb[i] = *(const float4*)(B + (size_t)(c >> 5) * ldb + ((c & 31) << 2));
    }
    for (int k0 = 0; k0 < K; k0 += KT) {
        __syncthreads();
#pragma unroll
        for (int i = 0; i < 4; i++) {
            int c = tid + 256 * i;
            *(float4*)(As + (c >> 3) * KT  + ((c & 7)  << 2)) = ra[i];
            *(float4*)(Bs + (c >> 5) * 128 + ((c & 31) << 2)) = rb[i];
        }
        __syncthreads();
        const int k1 = k0 + KT;
        if (k1 < K) {
#pragma unroll
            for (int i = 0; i < 4; i++) {
                int c = tid + 256 * i;
                ra[i] = *(const float4*)(A + (size_t)(c >> 3) * lda + k1 + ((c & 7) << 2));
                rb[i] = *(const float4*)(B + (size_t)(k1 + (c >> 5)) * ldb + ((c & 31) << 2));
            }
        }
#pragma unroll
        for (int k = 0; k < KT; k++) {
            const float* brow = Bs + k * 128 + tx * 8;
            ulonglong2 q0 = *(const ulonglong2*)brow;
            ulonglong2 q1 = *(const ulonglong2*)(brow + 4);
            u64 bp0 = q0.x, bp1 = q0.y, bp2 = q1.x, bp3 = q1.y;
#pragma unroll
            for (int i = 0; i < 8; i++) {
                float a = As[(ty * 8 + i) * KT + k];
                u64 ad;
                asm("mov.b64 %0, {%1, %1};" : "=l"(ad) : "f"(a));
                asm("fma.rn.f32x2 %0, %1, %2, %0;" : "+l"(acc[i][0]) : "l"(ad), "l"(bp0));
                asm("fma.rn.f32x2 %0, %1, %2, %0;" : "+l"(acc[i][1]) : "l"(ad), "l"(bp1));
                asm("fma.rn.f32x2 %0, %1, %2, %0;" : "+l"(acc[i][2]) : "l"(ad), "l"(bp2));
                asm("fma.rn.f32x2 %0, %1, %2, %0;" : "+l"(acc[i][3]) : "l"(ad), "l"(bp3));
            }
        }
    }
}
union F4U { u64 u[2]; float4 v; };

// ------------------------- prep kernels --------------------------------------
__global__ void k_hinit(const float* __restrict__ h_f, const float* __restrict__ h_b)
{
    int i = blockIdx.x * blockDim.x + threadIdx.x;
    if (i < 2 * Bsz * Hsz) {
        int dir = i >> 17, b = (i >> 10) & 127, k = i & 1023;
        g_h16[dir][b][k] = __float2half((dir ? h_b : h_f)[b * Hsz + k]);
    }
}

// nP = slice*64 + jh*32 + g*8 + jl3  <->  orig col = g*1024 + slice*16 + jh*8 + jl3
__global__ void __launch_bounds__(256) k_wprep(const float* __restrict__ W_f,
                                               const float* __restrict__ W_b)
{
    int bid   = blockIdx.x;                 // 8192 blocks
    int kblk  = bid & 15;
    int g     = (bid >> 4) & 3;
    int slice = (bid >> 6) & 63;
    int dir   = bid >> 12;
    const float* W = dir ? W_b : W_f;

    int jl = threadIdx.x >> 4;              // 0..15
    int kk = threadIdx.x & 15;
    int col = g * 1024 + slice * 16 + jl;
    int jh = jl >> 3, jl3 = jl & 7;
    int nP  = slice * 64 + jh * 32 + g * 8 + jl3;
#pragma unroll
    for (int r = 0; r < 4; r++) {
        int k = kblk * 64 + kk + r * 16;
        g_Wh[dir][nP][k] = __float2half(W[(size_t)(Hsz + k) * G4 + col]);
    }
}

__global__ void k_lutperm()
{
    int i = blockIdx.x * blockDim.x + threadIdx.x;
    if (i < 2 * Vsz * G4) {
        int d = i >> 19, v = (i >> 12) & 127, nP = i & 4095;
        int slice = nP >> 6, rem = nP & 63;
        int jh = rem >> 5, g = (rem >> 3) & 3, jl3 = rem & 7;
        g_lutP[d][v][nP] =
            g_token_gates[d][v][g * 1024 + slice * 16 + jh * 8 + jl3];
    }
}

__global__ void k_woutprep(const float* __restrict__ W_out)
{
    int i = blockIdx.x * blockDim.x + threadIdx.x;
    if (i < Vsz * 2 * Hsz) {
        int v = i >> 11, k = i & 2047;
        g_WoTh[v][k] = __float2half(W_out[(size_t)k * Vsz + v]);
    }
}

__global__ void __launch_bounds__(256) k_lut(
    const float* __restrict__ emb,
    const float* __restrict__ W_f, const float* __restrict__ b_f,
    const float* __restrict__ W_b, const float* __restrict__ b_b)
{
    __shared__ __align__(16) float As[128 * KT];
    __shared__ __align__(16) float Bs[KT * 128];
    int dir   = blockIdx.x >> 5;
    int slice = blockIdx.x & 31;
    const float* W    = dir ? W_b : W_f;
    const float* bias = dir ? b_b : b_f;

    u64 acc[8][4] = {};
    gemm_tile_K(emb, Hsz, W + slice * 128, G4, Hsz, acc, As, Bs);

    const int tx = threadIdx.x & 15, ty = threadIdx.x >> 4;
    float* C = &g_token_gates[dir][0][0] + slice * 128;
    float4 bv0 = *(const float4*)(bias + slice * 128 + tx * 8);
    float4 bv1 = *(const float4*)(bias + slice * 128 + tx * 8 + 4);
#pragma unroll
    for (int i = 0; i < 8; i++) {
        int r = ty * 8 + i;
        F4U u0; u0.u[0] = acc[i][0]; u0.u[1] = acc[i][1];
        F4U u1; u1.u[0] = acc[i][2]; u1.u[1] = acc[i][3];
        u0.v.x += bv0.x; u0.v.y += bv0.y; u0.v.z += bv0.z; u0.v.w += bv0.w;
        u1.v.x += bv1.x; u1.v.y += bv1.y; u1.v.z += bv1.z; u1.v.w += bv1.w;
        *(float4*)(C + (size_t)r * G4 + tx * 8)     = u0.v;
        *(float4*)(C + (size_t)r * G4 + tx * 8 + 4) = u1.v;
    }
}

// ------------------------- recurrence staging (k64 sub-blocks) ---------------
// sub-block layout: [0,16K) A 128 rows x 128B swz ; [16K,24K) W 64 rows x 128B
__device__ __forceinline__ void issue_subA(uint32_t sub, const char* pA,
                                           size_t koffB, int tid)
{
#pragma unroll
    for (int i = 0; i < 4; i++) {
        int idx = tid + 256 * i;
        int r = idx >> 3, seg = idx & 7;
        CPA(sub + swz(r * 128 + seg * 16),
            pA + (size_t)r * 2048 + koffB + seg * 16);
    }
}
__device__ __forceinline__ void issue_subW(uint32_t sub, const char* pWh,
                                           size_t koffB, int tid)
{
#pragma unroll
    for (int i = 0; i < 2; i++) {
        int idx = tid + 256 * i;
        int r = (idx >> 3) & 63, seg = idx & 7;
        CPA(sub + 16384 + swz(r * 128 + seg * 16),
            pWh + (size_t)r * 2048 + koffB + seg * 16);
    }
}

// k64 sub-block math (fp32 acc, warp layout 4 mrow x 2 ncol)
#define SUB_MATH(sub)                                                           \
    _Pragma("unroll")                                                           \
    for (int kk = 0; kk < 4; kk++) {                                            \
        const uint32_t koff = kk * 32 + lh * 16;                                \
        u32 ah0[4], ah1[4];                                                     \
        ldsm4(ah0, (sub) + swz((mrow * 32 + lr) * 128 + koff));                 \
        ldsm4(ah1, (sub) + swz((mrow * 32 + 16 + lr) * 128 + koff));            \
        const uint32_t wb2 = (sub) + 16384;                                     \
        _Pragma("unroll")                                                       \
        for (int nh = 0; nh < 2; nh++) {                                        \
            u32 wh[4];                                                          \
            uint32_t wro = swz((ncol * 32 + nh * 16 + lr) * 128 + koff);        \
            ldsm4(wh, wb2 + wro);                                               \
            mma_f16(d1[nh * 2],     ah0, wh[0], wh[2]);                         \
            mma_f16(d1[nh * 2 + 1], ah0, wh[1], wh[3]);                         \
            mma_f16(d1[4 + nh * 2],     ah1, wh[0], wh[2]);                     \
            mma_f16(d1[4 + nh * 2 + 1], ah1, wh[1], wh[3]);                     \
        }                                                                       \
    }

// ------------------------- persistent recurrence -----------------------------
// chunk schedule (k64 units): sizes {1,1,2,4,4,4}, offsets {0,1,2,4,8,12}
__global__ void __launch_bounds__(256, 1) k_recurrent(
    const int* __restrict__ x,
    const float* __restrict__ c_f, const float* __restrict__ c_b)
{
    extern __shared__ __align__(128) char dsm[];
    const uint32_t sb = smem_u32(dsm);

    const int tid  = threadIdx.x;
    const int w    = tid >> 5, lane = tid & 31;
    const int lr   = lane & 15, lh = lane >> 4;
    const int q    = lane & 3,  r0 = lane >> 2;
    const int blk  = blockIdx.x;
    const int dir  = blk >> 6, slice = blk & 63;
    const int n0   = slice * 64, j0 = slice * 16;
    const int mrow = w >> 1, ncol = w & 1;

    const int NKC[6] = {1, 1, 2, 4, 4, 4};
    const int CUM[6] = {0, 1, 2, 4, 8, 12};

    float c_reg[8];
    {
        const float* cin = dir ? c_b : c_f;
#pragma unroll
        for (int ci = 0; ci < 8; ci++) {
            int mt = ci >> 2, rr = (ci >> 1) & 1, jj = ci & 1;
            int b  = mrow * 32 + mt * 16 + rr * 8 + r0;
            int jl = ncol * 8 + 2 * q + jj;
            c_reg[ci] = cin[(size_t)b * Hsz + j0 + jl];
        }
    }

    const char* pWh = (const char*)&g_Wh[dir][n0][0];
    u32* cnt = &g_cnt[dir];

    // pre-stage W of chunk 0 (k64, h-independent) into buffer 0
    issue_subW(sb, pWh, 0, tid);
    asm volatile("cp.async.commit_group;" ::: "memory");

    for (int s = 0; s < Ssz; s++) {
        const int ts = dir ? (Ssz - 1 - s) : s;
        const char* pA = (s == 0)
            ? (const char*)&g_h16[dir][0][0]
            : (const char*)&g_out16[dir][dir ? (Ssz - s) : (s - 1)][0][0];

        // one-sided wait: h(s) fully published when cnt >= 64*s
        if (s > 0) {
            if (tid == 0) {
                const u32 tgt = (u32)(NBD * s);
                u32 v;
                do {
                    asm volatile("ld.acquire.gpu.global.u32 %0, [%1];"
                                 : "=r"(v) : "l"(cnt) : "memory");
                } while (v < tgt);
            }
            __syncthreads();
        }
        // stage A of chunk 0 (k64 only -> minimal exposed latency)
        issue_subA(sb, pA, 0, tid);
        asm volatile("cp.async.commit_group;" ::: "memory");

        // LUT prefetch (hides L2 latency under the GEMM)
        float2 lp[2][2][4];
#pragma unroll
        for (int mt = 0; mt < 2; mt++)
#pragma unroll
            for (int rr = 0; rr < 2; rr++) {
                const int b = mrow * 32 + mt * 16 + rr * 8 + r0;
                const int tok = __ldg(&x[b * Ssz + ts]);
                const float* lutb = &g_lutP[dir][tok][n0 + ncol * 32];
#pragma unroll
                for (int g = 0; g < 4; g++)
                    lp[mt][rr][g] = *(const float2*)(lutb + g * 8 + 2 * q);
            }

        float d1[8][4];
#pragma unroll
        for (int i = 0; i < 8; i++)
#pragma unroll
            for (int r = 0; r < 4; r++) d1[i][r] = 0.f;

#pragma unroll
        for (int c = 0; c < 6; c++) {
            asm volatile("cp.async.wait_group 0;" ::: "memory");
            __syncthreads();
            if (c < 5) {
                const uint32_t nbuf = sb + ((c + 1) & 1) * RBUF_R;
#pragma unroll
                for (int b2 = 0; b2 < 4; b2++) {
                    if (b2 < NKC[c + 1]) {
                        const size_t koffB = (size_t)(CUM[c + 1] + b2) * 128;
                        issue_subA(nbuf + b2 * SUBB, pA, koffB, tid);
                        issue_subW(nbuf + b2 * SUBB, pWh, koffB, tid);
                    }
                }
                asm volatile("cp.async.commit_group;" ::: "memory");
            }
            const uint32_t cbuf = sb + (c & 1) * RBUF_R;
#pragma unroll
            for (int b2 = 0; b2 < 4; b2++) {
                if (b2 < NKC[c]) {
                    const uint32_t sub = cbuf + b2 * SUBB;
                    SUB_MATH(sub)
                }
            }
        }

        // ---- epilogue: thread-local LSTM update; publish h(s+1) ----
#pragma unroll
        for (int mt = 0; mt < 2; mt++) {
#pragma unroll
            for (int rr = 0; rr < 2; rr++) {
                const int b = mrow * 32 + mt * 16 + rr * 8 + r0;
                float hv[2];
#pragma unroll
                for (int jj = 0; jj < 2; jj++) {
                    const int ri = rr * 2 + jj;
                    float zi = d1[mt*4+0][ri] + (jj ? lp[mt][rr][0].y : lp[mt][rr][0].x);
                    float zf = d1[mt*4+1][ri] + (jj ? lp[mt][rr][1].y : lp[mt][rr][1].x);
                    float zo = d1[mt*4+2][ri] + (jj ? lp[mt][rr][2].y : lp[mt][rr][2].x);
                    float zg = d1[mt*4+3][ri] + (jj ? lp[mt][rr][3].y : lp[mt][rr][3].x);
                    float ig = sigmoid_fast(zi);
                    float fg = sigmoid_fast(zf);
                    float og = sigmoid_fast(zo);
                    const int ci = mt * 4 + rr * 2 + jj;
                    float cc = fg * c_reg[ci] + ig * tanh_fast(zg);
                    c_reg[ci] = cc;
                    hv[jj] = og * tanh_fast(cc);
                }
                __half2 hp = __floats2half2_rn(hv[0], hv[1]);
                const int jcol = j0 + ncol * 8 + 2 * q;
                *(u32*)(&g_out16[dir][ts][b][jcol]) = *(u32*)&hp;
                if (s == Ssz - 1)
                    *(float2*)(&g_hfin[dir][b][jcol]) = make_float2(hv[0], hv[1]);
            }
        }

        // publish FIRST (critical path), then pre-stage next step's W chunk 0
        __syncthreads();
        if (tid == 0)
            asm volatile("red.release.gpu.global.add.u32 [%0], %1;"
                         :: "l"(cnt), "r"(1u) : "memory");

        if (s < Ssz - 1) {
            // buffer 0 is free: its last math was chunk 4; chunk 5 used buffer 1
            issue_subW(sb, pWh, 0, tid);
            asm volatile("cp.async.commit_group;" ::: "memory");
        }
    }

    // final c writeback
#pragma unroll
    for (int ci = 0; ci < 8; ci++) {
        int mt = ci >> 2, rr = (ci >> 1) & 1, jj = ci & 1;
        int b  = mrow * 32 + mt * 16 + rr * 8 + r0;
        int jl = ncol * 8 + 2 * q + jj;
        g_cfin[dir][b][j0 + jl] = c_reg[ci];
    }

    // reset the counter for the next graph replay (after all CTAs stop polling)
    grid_barrier_dir(dir);
    if (slice == 0 && tid == 0) *cnt = 0;
}

// ------------------------- HMMA output projection (1-product) ----------------
__device__ __forceinline__ void proj_issue(uint32_t buf, int t,
    const char* pW0, int kc, int tid)
{
    const int dirc = kc >> 3;
    const char* pA = (const char*)&g_out16[dirc][t][0][0];
    const size_t kb = (size_t)(kc & 7) * 256;
#pragma unroll
    for (int i = 0; i < 8; i++) {
        int idx = tid + 256 * i;
        int kh = idx >> 10, r = (idx >> 3) & 127, seg = idx & 7;
        CPA(buf + kh * 16384 + swz(r * 128 + seg * 16),
            pA + (size_t)r * 2048 + kb + kh * 128 + seg * 16);
    }
    const size_t kbw = (size_t)kc * 256;
#pragma unroll
    for (int i = 0; i < 4; i++) {
        int idx = tid + 256 * i;
        int kh = idx >> 9, r = (idx >> 3) & 63, seg = idx & 7;
        CPA(buf + 32768 + kh * 8192 + swz(r * 128 + seg * 16),
            pW0 + (size_t)r * 4096 + kbw + kh * 128 + seg * 16);
    }
    asm volatile("cp.async.commit_group;" ::: "memory");
}

#define CHUNK_MATH_P(base)                                                      \
    _Pragma("unroll")                                                           \
    for (int kk = 0; kk < 8; kk++) {                                            \
        const int kh = kk >> 2;                                                 \
        const uint32_t koff = (kk & 3) * 32 + lh * 16;                          \
        const uint32_t ab = (base) + kh * 16384;                                \
        u32 ah0[4], ah1[4];                                                     \
        ldsm4(ah0, ab + swz((mrow * 32 + lr) * 128 + koff));                    \
        ldsm4(ah1, ab + swz((mrow * 32 + 16 + lr) * 128 + koff));               \
        const uint32_t wb = (base) + 32768 + kh * 8192;                         \
        _Pragma("unroll")                                                       \
        for (int nh = 0; nh < 2; nh++) {                                        \
            u32 wh[4];                                                          \
            uint32_t wro = swz((ncol * 32 + nh * 16 + lr) * 128 + koff);        \
            ldsm4(wh, wb + wro);                                                \
            mma_f16(d1[nh * 2],     ah0, wh[0], wh[2]);                         \
            mma_f16(d1[nh * 2 + 1], ah0, wh[1], wh[3]);                         \
            mma_f16(d1[4 + nh * 2],     ah1, wh[0], wh[2]);                     \
            mma_f16(d1[4 + nh * 2 + 1], ah1, wh[1], wh[3]);                     \
        }                                                                       \
    }

__global__ void __launch_bounds__(256, 1) k_proj_h(
    const float* __restrict__ b_out, float* __restrict__ out)
{
    extern __shared__ __align__(128) char dsm[];
    const uint32_t sb = smem_u32(dsm);

    const int tid  = threadIdx.x;
    const int w    = tid >> 5, lane = tid & 31;
    const int lr   = lane & 15, lh = lane >> 4;
    const int q    = lane & 3,  r0 = lane >> 2;
    const int bid  = blockIdx.x;          // 1024
    const int t    = bid >> 1, vh = bid & 1;
    const int mrow = w >> 1, ncol = w & 1;

    const char* pW0 = (const char*)&g_WoTh[vh * 64][0];

    float d1[8][4] = {};
    proj_issue(sb, t, pW0, 0, tid);

    for (int kc = 0; kc < 16; kc++) {
        asm volatile("cp.async.wait_group 0;" ::: "memory");
        __syncthreads();
        if (kc < 15)
            proj_issue(sb + ((kc + 1) & 1) * RBUF_P, t, pW0, kc + 1, tid);
        const uint32_t base = sb + (kc & 1) * RBUF_P;
        CHUNK_MATH_P(base)
    }

#pragma unroll
    for (int mt = 0; mt < 2; mt++) {
#pragma unroll
        for (int rr = 0; rr < 2; rr++) {
            const int b = mrow * 32 + mt * 16 + rr * 8 + r0;
#pragma unroll
            for (int nt = 0; nt < 4; nt++) {
                const int v = vh * 64 + ncol * 32 + nt * 8 + 2 * q;
                float2 bv = *(const float2*)(b_out + v);
                float2 o;
                o.x = d1[mt*4+nt][rr*2+0] + bv.x;
                o.y = d1[mt*4+nt][rr*2+1] + bv.y;
                *(float2*)(out + ((size_t)b * Ssz + t) * Vsz + v) = o;
            }
        }
    }
}

// ------------------------- final state writeback ------------------------------
__global__ void k_states(float* __restrict__ out)
{
    int i = blockIdx.x * blockDim.x + threadIdx.x;
    if (i < Bsz * Hsz) {
        int b = i >> 10, j = i & 1023;
        size_t base = (size_t)Bsz * Ssz * Vsz;
        out[base + 0 * Bsz * Hsz + i] = g_hfin[0][b][j];
        out[base + 1 * Bsz * Hsz + i] = g_hfin[1][b][j];
        out[base + 2 * Bsz * Hsz + i] = g_cfin[0][b][j];
        out[base + 3 * Bsz * Hsz + i] = g_cfin[1][b][j];
    }
}

// ---------------------------------------------------------------------------
extern "C" void kernel_launch(void* const* d_in, const int* in_sizes, int n_in,
                              void* d_out, int out_size)
{
    const int*   x     = (const int*)  d_in[0];
    const float* h_f   = (const float*)d_in[1];
    const float* h_b   = (const float*)d_in[2];
    const float* c_f   = (const float*)d_in[3];
    const float* c_b   = (const float*)d_in[4];
    const float* emb   = (const float*)d_in[5];
    const float* W_f   = (const float*)d_in[6];
    const float* b_f   = (const float*)d_in[7];
    const float* W_b   = (const float*)d_in[8];
    const float* b_b   = (const float*)d_in[9];
    const float* W_out = (const float*)d_in[10];
    const float* b_out = (const float*)d_in[11];
    float* out = (float*)d_out;

    static bool attr_done = false;
    if (!attr_done) {
        cudaFuncSetAttribute(k_recurrent,
                             cudaFuncAttributeMaxDynamicSharedMemorySize, SMEM_REC);
        cudaFuncSetAttribute(k_proj_h,
                             cudaFuncAttributeMaxDynamicSharedMemorySize, SMEM_PROJ);
        attr_done = true;
    }

    k_hinit<<<1024, 256>>>(h_f, h_b);
    k_wprep<<<8192, 256>>>(W_f, W_b);
    k_lut<<<64, 256>>>(emb, W_f, b_f, W_b, b_b);
    k_lutperm<<<4096, 256>>>();
    k_woutprep<<<1024, 256>>>(W_out);

    k_recurrent<<<NB, 256, SMEM_REC>>>(x, c_f, c_b);

    k_proj_h<<<1024, 256, SMEM_PROJ>>>(b_out, out);
    if (out_size >= (int)((size_t)Bsz * Ssz * Vsz + 4 * Bsz * Hsz))
        k_states<<<512, 256>>>(out);
}

// round 17
// speedup vs baseline: 1.1709x; 1.0037x over previous
#include <cuda_runtime.h>
#include <cuda_fp16.h>
#include <math.h>
#include <stdint.h>

// ---------------------------------------------------------------------------
// BLSTM: B=128, S=512, H=1024, VOCAB=128
// fp16 HMMA recurrence (fp32 acc), one-sided per-direction counter with
// red.release publish, progressive chunk schedule, W chunk-0 pre-staged.
// 1-product HMMA output projection. Coalesced transpose wprep + fused lut.
// ---------------------------------------------------------------------------

#define Bsz   128
#define Ssz   512
#define Hsz   1024
#define Vsz   128
#define G4    4096
#define KT    32
#define NB    128
#define NBD   64        // CTAs per direction

// recurrence: sub-block = A 16K + W 8K = 24 KB; buffer = 4 sub-blocks = 96 KB
#define SUBB      24576
#define RBUF_R    (4 * SUBB)
#define SMEM_REC  (2 * RBUF_R)
// projection buffer: A 32K | Wh 16K = 48 KB ; double = 96 KB
#define RBUF_P    49152
#define SMEM_PROJ (2 * RBUF_P)

typedef unsigned long long u64;
typedef unsigned int u32;

// ------------------------- device scratch -----------------------------------
__device__ float  g_lutP[2][Vsz][G4];              // LUT, gate-permuted (nP)
__device__ __half g_h16[2][Bsz][Hsz];              // initial h only
__device__ __half g_Wh[2][G4][Hsz];                // W^T fp16 (permuted nP)
__device__ __half g_out16[2][Ssz][Bsz][Hsz];       // h history fp16 (= exchange)
__device__ __half g_WoTh[Vsz][2 * Hsz];            // W_out^T fp16
__device__ float  g_hfin[2][Bsz][Hsz];
__device__ float  g_cfin[2][Bsz][Hsz];
__device__ u32    g_cnt[2];                        // per-dir step-completion count
__device__ volatile unsigned g_gen2[2];
__device__ unsigned g_count2[2];

// ------------------------- helpers ------------------------------------------
static __device__ __forceinline__ uint32_t smem_u32(const void* p) {
    uint32_t a;
    asm("{ .reg .u64 t; cvta.to.shared.u64 t, %1; cvt.u32.u64 %0, t; }"
        : "=r"(a) : "l"(p));
    return a;
}
static __device__ __forceinline__ uint32_t swz(uint32_t o) {
    return o ^ ((o >> 3) & 0x70);
}
#define CPA(dst, src) \
    asm volatile("cp.async.cg.shared.global [%0], [%1], 16;" \
                 :: "r"(dst), "l"(src) : "memory")

static __device__ __forceinline__ void ldsm4(u32 r[4], u32 addr) {
    asm volatile("ldmatrix.sync.aligned.m8n8.x4.shared.b16 {%0,%1,%2,%3}, [%4];"
                 : "=r"(r[0]), "=r"(r[1]), "=r"(r[2]), "=r"(r[3]) : "r"(addr));
}
static __device__ __forceinline__ void mma_f16(float d[4], const u32 a[4],
                                               u32 b0, u32 b1) {
    asm volatile(
        "mma.sync.aligned.m16n8k16.row.col.f32.f16.f16.f32 "
        "{%0,%1,%2,%3}, {%4,%5,%6,%7}, {%8,%9}, {%0,%1,%2,%3};"
        : "+f"(d[0]), "+f"(d[1]), "+f"(d[2]), "+f"(d[3])
        : "r"(a[0]), "r"(a[1]), "r"(a[2]), "r"(a[3]), "r"(b0), "r"(b1));
}
static __device__ __forceinline__ float tanh_fast(float v) {
    return 1.f - 2.f / (1.f + __expf(2.f * v));
}
static __device__ __forceinline__ float sigmoid_fast(float v) {
    return 1.f / (1.f + __expf(-v));
}

// ------------------------- per-direction barrier (end-of-kernel only) --------
__device__ __forceinline__ void grid_barrier_dir(int dir)
{
    __syncthreads();
    if (threadIdx.x == 0) {
        unsigned gen = g_gen2[dir];
        __threadfence();
        unsigned t = atomicAdd(&g_count2[dir], 1);
        if (t == NBD - 1) {
            g_count2[dir] = 0;
            __threadfence();
            g_gen2[dir] = gen + 1;
        } else {
            while (g_gen2[dir] == gen) {}
        }
        __threadfence();
    }
    __syncthreads();
}

// ------------------------- FFMA GEMM core (lut only) -------------------------
__device__ __forceinline__ void gemm_tile_K(
    const float* __restrict__ A, int lda,
    const float* __restrict__ B, int ldb,
    int K, u64 acc[8][4],
    float* As, float* Bs)
{
    const int tid = threadIdx.x;
    const int tx  = tid & 15;
    const int ty  = tid >> 4;

    float4 ra[4], rb[4];
#pragma unroll
    for (int i = 0; i < 4; i++) {
        int c = tid + 256 * i;
        ra[i] = *(const float4*)(A + (size_t)(c >> 3) * lda + ((c & 7) << 2));
        rb[i] = *(const float4*)(B + (size_t)(c >> 5) * ldb + ((c & 31) << 2));
    }
    for (int k0 = 0; k0 < K; k0 += KT) {
        __syncthreads();
#pragma unroll
        for (int i = 0; i < 4; i++) {
            int c = tid + 256 * i;
            *(float4*)(As + (c >> 3) * KT  + ((c & 7)  << 2)) = ra[i];
            *(float4*)(Bs + (c >> 5) * 128 + ((c & 31) << 2)) = rb[i];
        }
        __syncthreads();
        const int k1 = k0 + KT;
        if (k1 < K) {
#pragma unroll
            for (int i = 0; i < 4; i++) {
                int c = tid + 256 * i;
                ra[i] = *(const float4*)(A + (size_t)(c >> 3) * lda + k1 + ((c & 7) << 2));
                rb[i] = *(const float4*)(B + (size_t)(k1 + (c >> 5)) * ldb + ((c & 31) << 2));
            }
        }
#pragma unroll
        for (int k = 0; k < KT; k++) {
            const float* brow = Bs + k * 128 + tx * 8;
            ulonglong2 q0 = *(const ulonglong2*)brow;
            ulonglong2 q1 = *(const ulonglong2*)(brow + 4);
            u64 bp0 = q0.x, bp1 = q0.y, bp2 = q1.x, bp3 = q1.y;
#pragma unroll
            for (int i = 0; i < 8; i++) {
                float a = As[(ty * 8 + i) * KT + k];
                u64 ad;
                asm("mov.b64 %0, {%1, %1};" : "=l"(ad) : "f"(a));
                asm("fma.rn.f32x2 %0, %1, %2, %0;" : "+l"(acc[i][0]) : "l"(ad), "l"(bp0));
                asm("fma.rn.f32x2 %0, %1, %2, %0;" : "+l"(acc[i][1]) : "l"(ad), "l"(bp1));
                asm("fma.rn.f32x2 %0, %1, %2, %0;" : "+l"(acc[i][2]) : "l"(ad), "l"(bp2));
                asm("fma.rn.f32x2 %0, %1, %2, %0;" : "+l"(acc[i][3]) : "l"(ad), "l"(bp3));
            }
        }
    }
}
union F4U { u64 u[2]; float4 v; };

// ------------------------- prep kernels --------------------------------------
__global__ void k_hinit(const float* __restrict__ h_f, const float* __restrict__ h_b)
{
    int i = blockIdx.x * blockDim.x + threadIdx.x;
    if (i < 2 * Bsz * Hsz) {
        int dir = i >> 17, b = (i >> 10) & 127, k = i & 1023;
        g_h16[dir][b][k] = __float2half((dir ? h_b : h_f)[b * Hsz + k]);
    }
}

// Coalesced transpose wprep: block = (dir, slice, kblk of 128 k-rows).
// Phase 1: read 64B col-segments of W (coalesced), fp16-convert into smem
// transposed tile. Phase 2: write 64 permuted rows x 128 k coalesced.
// nP = slice*64 + jh*32 + g*8 + jl3  <->  orig col = g*1024 + slice*16 + jh*8 + jl3
__global__ void __launch_bounds__(256) k_wprep(const float* __restrict__ W_f,
                                               const float* __restrict__ W_b)
{
    __shared__ __half s[64][136];           // [nP local][k], pad 8 halves
    const int bid   = blockIdx.x;           // 1024 blocks
    const int kblk  = bid & 7;
    const int slice = (bid >> 3) & 63;
    const int dir   = bid >> 9;
    const float* W  = dir ? W_b : W_f;
    const int tid = threadIdx.x;
    const int j   = tid & 15;               // col within 16
    const int pr  = tid >> 4;               // 0..15

    // phase 1: 32 passes x 16 (k,g) pairs; each 16-thread group reads 64 B
#pragma unroll 4
    for (int pass = 0; pass < 32; pass++) {
        int pairi = pass * 16 + pr;         // 0..511
        int g = pairi & 3;
        int k = pairi >> 2;                 // 0..127
        float v = W[(size_t)(Hsz + kblk * 128 + k) * G4 + g * 1024 + slice * 16 + j];
        s[(j >> 3) * 32 + g * 8 + (j & 7)][k] = __float2half(v);
    }
    __syncthreads();

    // phase 2: 64 rows x 128 fp16 (256 B/row), 4 threads per row
    const int row = tid >> 2, seg = tid & 3;
    const __half* src = &s[row][seg * 32];
    __half* dst = &g_Wh[dir][slice * 64 + row][kblk * 128 + seg * 32];
#pragma unroll
    for (int i = 0; i < 4; i++)
        *(float4*)(dst + i * 8) = *(const float4*)(src + i * 8);
}

__global__ void k_woutprep(const float* __restrict__ W_out)
{
    int i = blockIdx.x * blockDim.x + threadIdx.x;
    if (i < Vsz * 2 * Hsz) {
        int v = i >> 11, k = i & 2047;
        g_WoTh[v][k] = __float2half(W_out[(size_t)k * Vsz + v]);
    }
}

// token-gate LUT: writes DIRECTLY into permuted g_lutP (k_lutperm fused).
// orig col n = slice*128 + tx*8 + {0..7}: the 8 share (g, s16, jh), jl3 = 0..7
// -> 8 consecutive permuted cols at nP = s16*64 + jh*32 + g*8.
__global__ void __launch_bounds__(256) k_lut(
    const float* __restrict__ emb,
    const float* __restrict__ W_f, const float* __restrict__ b_f,
    const float* __restrict__ W_b, const float* __restrict__ b_b)
{
    __shared__ __align__(16) float As[128 * KT];
    __shared__ __align__(16) float Bs[KT * 128];
    int dir   = blockIdx.x >> 5;
    int slice = blockIdx.x & 31;
    const float* W    = dir ? W_b : W_f;
    const float* bias = dir ? b_b : b_f;

    u64 acc[8][4] = {};
    gemm_tile_K(emb, Hsz, W + slice * 128, G4, Hsz, acc, As, Bs);

    const int tx = threadIdx.x & 15, ty = threadIdx.x >> 4;
    const int n   = slice * 128 + tx * 8;        // orig col base (8-aligned)
    const int g   = n >> 10;
    const int s16 = (n & 1023) >> 4;
    const int jh  = (n >> 3) & 1;
    const int nP  = s16 * 64 + jh * 32 + g * 8;  // permuted col base
    float4 bv0 = *(const float4*)(bias + n);
    float4 bv1 = *(const float4*)(bias + n + 4);
#pragma unroll
    for (int i = 0; i < 8; i++) {
        int r = ty * 8 + i;
        F4U u0; u0.u[0] = acc[i][0]; u0.u[1] = acc[i][1];
        F4U u1; u1.u[0] = acc[i][2]; u1.u[1] = acc[i][3];
        u0.v.x += bv0.x; u0.v.y += bv0.y; u0.v.z += bv0.z; u0.v.w += bv0.w;
        u1.v.x += bv1.x; u1.v.y += bv1.y; u1.v.z += bv1.z; u1.v.w += bv1.w;
        float* dst = &g_lutP[dir][r][nP];
        *(float4*)dst       = u0.v;
        *(float4*)(dst + 4) = u1.v;
    }
}

// ------------------------- recurrence staging (k64 sub-blocks) ---------------
// sub-block layout: [0,16K) A 128 rows x 128B swz ; [16K,24K) W 64 rows x 128B
__device__ __forceinline__ void issue_subA(uint32_t sub, const char* pA,
                                           size_t koffB, int tid)
{
#pragma unroll
    for (int i = 0; i < 4; i++) {
        int idx = tid + 256 * i;
        int r = idx >> 3, seg = idx & 7;
        CPA(sub + swz(r * 128 + seg * 16),
            pA + (size_t)r * 2048 + koffB + seg * 16);
    }
}
__device__ __forceinline__ void issue_subW(uint32_t sub, const char* pWh,
                                           size_t koffB, int tid)
{
#pragma unroll
    for (int i = 0; i < 2; i++) {
        int idx = tid + 256 * i;
        int r = (idx >> 3) & 63, seg = idx & 7;
        CPA(sub + 16384 + swz(r * 128 + seg * 16),
            pWh + (size_t)r * 2048 + koffB + seg * 16);
    }
}

// k64 sub-block math (fp32 acc, warp layout 4 mrow x 2 ncol)
#define SUB_MATH(sub)                                                           \
    _Pragma("unroll")                                                           \
    for (int kk = 0; kk < 4; kk++) {                                            \
        const uint32_t koff = kk * 32 + lh * 16;                                \
        u32 ah0[4], ah1[4];                                                     \
        ldsm4(ah0, (sub) + swz((mrow * 32 + lr) * 128 + koff));                 \
        ldsm4(ah1, (sub) + swz((mrow * 32 + 16 + lr) * 128 + koff));            \
        const uint32_t wb2 = (sub) + 16384;                                     \
        _Pragma("unroll")                                                       \
        for (int nh = 0; nh < 2; nh++) {                                        \
            u32 wh[4];                                                          \
            uint32_t wro = swz((ncol * 32 + nh * 16 + lr) * 128 + koff);        \
            ldsm4(wh, wb2 + wro);                                               \
            mma_f16(d1[nh * 2],     ah0, wh[0], wh[2]);                         \
            mma_f16(d1[nh * 2 + 1], ah0, wh[1], wh[3]);                         \
            mma_f16(d1[4 + nh * 2],     ah1, wh[0], wh[2]);                     \
            mma_f16(d1[4 + nh * 2 + 1], ah1, wh[1], wh[3]);                     \
        }                                                                       \
    }

// ------------------------- persistent recurrence -----------------------------
// chunk schedule (k64 units): sizes {1,1,2,4,4,4}, offsets {0,1,2,4,8,12}
__global__ void __launch_bounds__(256, 1) k_recurrent(
    const int* __restrict__ x,
    const float* __restrict__ c_f, const float* __restrict__ c_b)
{
    extern __shared__ __align__(128) char dsm[];
    const uint32_t sb = smem_u32(dsm);

    const int tid  = threadIdx.x;
    const int w    = tid >> 5, lane = tid & 31;
    const int lr   = lane & 15, lh = lane >> 4;
    const int q    = lane & 3,  r0 = lane >> 2;
    const int blk  = blockIdx.x;
    const int dir  = blk >> 6, slice = blk & 63;
    const int n0   = slice * 64, j0 = slice * 16;
    const int mrow = w >> 1, ncol = w & 1;

    const int NKC[6] = {1, 1, 2, 4, 4, 4};
    const int CUM[6] = {0, 1, 2, 4, 8, 12};

    float c_reg[8];
    {
        const float* cin = dir ? c_b : c_f;
#pragma unroll
        for (int ci = 0; ci < 8; ci++) {
            int mt = ci >> 2, rr = (ci >> 1) & 1, jj = ci & 1;
            int b  = mrow * 32 + mt * 16 + rr * 8 + r0;
            int jl = ncol * 8 + 2 * q + jj;
            c_reg[ci] = cin[(size_t)b * Hsz + j0 + jl];
        }
    }

    const char* pWh = (const char*)&g_Wh[dir][n0][0];
    u32* cnt = &g_cnt[dir];

    // pre-stage W of chunk 0 (k64, h-independent) into buffer 0
    issue_subW(sb, pWh, 0, tid);
    asm volatile("cp.async.commit_group;" ::: "memory");

    for (int s = 0; s < Ssz; s++) {
        const int ts = dir ? (Ssz - 1 - s) : s;
        const char* pA = (s == 0)
            ? (const char*)&g_h16[dir][0][0]
            : (const char*)&g_out16[dir][dir ? (Ssz - s) : (s - 1)][0][0];

        // one-sided wait: h(s) fully published when cnt >= 64*s
        if (s > 0) {
            if (tid == 0) {
                const u32 tgt = (u32)(NBD * s);
                u32 v;
                do {
                    asm volatile("ld.acquire.gpu.global.u32 %0, [%1];"
                                 : "=r"(v) : "l"(cnt) : "memory");
                } while (v < tgt);
            }
            __syncthreads();
        }
        // stage A of chunk 0 (k64 only -> minimal exposed latency)
        issue_subA(sb, pA, 0, tid);
        asm volatile("cp.async.commit_group;" ::: "memory");

        // LUT prefetch (hides L2 latency under the GEMM)
        float2 lp[2][2][4];
#pragma unroll
        for (int mt = 0; mt < 2; mt++)
#pragma unroll
            for (int rr = 0; rr < 2; rr++) {
                const int b = mrow * 32 + mt * 16 + rr * 8 + r0;
                const int tok = __ldg(&x[b * Ssz + ts]);
                const float* lutb = &g_lutP[dir][tok][n0 + ncol * 32];
#pragma unroll
                for (int g = 0; g < 4; g++)
                    lp[mt][rr][g] = *(const float2*)(lutb + g * 8 + 2 * q);
            }

        float d1[8][4];
#pragma unroll
        for (int i = 0; i < 8; i++)
#pragma unroll
            for (int r = 0; r < 4; r++) d1[i][r] = 0.f;

#pragma unroll
        for (int c = 0; c < 6; c++) {
            asm volatile("cp.async.wait_group 0;" ::: "memory");
            __syncthreads();
            if (c < 5) {
                const uint32_t nbuf = sb + ((c + 1) & 1) * RBUF_R;
#pragma unroll
                for (int b2 = 0; b2 < 4; b2++) {
                    if (b2 < NKC[c + 1]) {
                        const size_t koffB = (size_t)(CUM[c + 1] + b2) * 128;
                        issue_subA(nbuf + b2 * SUBB, pA, koffB, tid);
                        issue_subW(nbuf + b2 * SUBB, pWh, koffB, tid);
                    }
                }
                asm volatile("cp.async.commit_group;" ::: "memory");
            }
            const uint32_t cbuf = sb + (c & 1) * RBUF_R;
#pragma unroll
            for (int b2 = 0; b2 < 4; b2++) {
                if (b2 < NKC[c]) {
                    const uint32_t sub = cbuf + b2 * SUBB;
                    SUB_MATH(sub)
                }
            }
        }

        // ---- epilogue: thread-local LSTM update; publish h(s+1) ----
#pragma unroll
        for (int mt = 0; mt < 2; mt++) {
#pragma unroll
            for (int rr = 0; rr < 2; rr++) {
                const int b = mrow * 32 + mt * 16 + rr * 8 + r0;
                float hv[2];
#pragma unroll
                for (int jj = 0; jj < 2; jj++) {
                    const int ri = rr * 2 + jj;
                    float zi = d1[mt*4+0][ri] + (jj ? lp[mt][rr][0].y : lp[mt][rr][0].x);
                    float zf = d1[mt*4+1][ri] + (jj ? lp[mt][rr][1].y : lp[mt][rr][1].x);
                    float zo = d1[mt*4+2][ri] + (jj ? lp[mt][rr][2].y : lp[mt][rr][2].x);
                    float zg = d1[mt*4+3][ri] + (jj ? lp[mt][rr][3].y : lp[mt][rr][3].x);
                    float ig = sigmoid_fast(zi);
                    float fg = sigmoid_fast(zf);
                    float og = sigmoid_fast(zo);
                    const int ci = mt * 4 + rr * 2 + jj;
                    float cc = fg * c_reg[ci] + ig * tanh_fast(zg);
                    c_reg[ci] = cc;
                    hv[jj] = og * tanh_fast(cc);
                }
                __half2 hp = __floats2half2_rn(hv[0], hv[1]);
                const int jcol = j0 + ncol * 8 + 2 * q;
                *(u32*)(&g_out16[dir][ts][b][jcol]) = *(u32*)&hp;
                if (s == Ssz - 1)
                    *(float2*)(&g_hfin[dir][b][jcol]) = make_float2(hv[0], hv[1]);
            }
        }

        // publish FIRST (critical path), then pre-stage next step's W chunk 0
        __syncthreads();
        if (tid == 0)
            asm volatile("red.release.gpu.global.add.u32 [%0], %1;"
                         :: "l"(cnt), "r"(1u) : "memory");

        if (s < Ssz - 1) {
            // buffer 0 is free: its last math was chunk 4; chunk 5 used buffer 1
            issue_subW(sb, pWh, 0, tid);
            asm volatile("cp.async.commit_group;" ::: "memory");
        }
    }

    // final c writeback
#pragma unroll
    for (int ci = 0; ci < 8; ci++) {
        int mt = ci >> 2, rr = (ci >> 1) & 1, jj = ci & 1;
        int b  = mrow * 32 + mt * 16 + rr * 8 + r0;
        int jl = ncol * 8 + 2 * q + jj;
        g_cfin[dir][b][j0 + jl] = c_reg[ci];
    }

    // reset the counter for the next graph replay (after all CTAs stop polling)
    grid_barrier_dir(dir);
    if (slice == 0 && tid == 0) *cnt = 0;
}

// ------------------------- HMMA output projection (1-product) ----------------
__device__ __forceinline__ void proj_issue(uint32_t buf, int t,
    const char* pW0, int kc, int tid)
{
    const int dirc = kc >> 3;
    const char* pA = (const char*)&g_out16[dirc][t][0][0];
    const size_t kb = (size_t)(kc & 7) * 256;
#pragma unroll
    for (int i = 0; i < 8; i++) {
        int idx = tid + 256 * i;
        int kh = idx >> 10, r = (idx >> 3) & 127, seg = idx & 7;
        CPA(buf + kh * 16384 + swz(r * 128 + seg * 16),
            pA + (size_t)r * 2048 + kb + kh * 128 + seg * 16);
    }
    const size_t kbw = (size_t)kc * 256;
#pragma unroll
    for (int i = 0; i < 4; i++) {
        int idx = tid + 256 * i;
        int kh = idx >> 9, r = (idx >> 3) & 63, seg = idx & 7;
        CPA(buf + 32768 + kh * 8192 + swz(r * 128 + seg * 16),
            pW0 + (size_t)r * 4096 + kbw + kh * 128 + seg * 16);
    }
    asm volatile("cp.async.commit_group;" ::: "memory");
}

#define CHUNK_MATH_P(base)                                                      \
    _Pragma("unroll")                                                           \
    for (int kk = 0; kk < 8; kk++) {                                            \
        const int kh = kk >> 2;                                                 \
        const uint32_t koff = (kk & 3) * 32 + lh * 16;                          \
        const uint32_t ab = (base) + kh * 16384;                                \
        u32 ah0[4], ah1[4];                                                     \
        ldsm4(ah0, ab + swz((mrow * 32 + lr) * 128 + koff));                    \
        ldsm4(ah1, ab + swz((mrow * 32 + 16 + lr) * 128 + koff));               \
        const uint32_t wb = (base) + 32768 + kh * 8192;                         \
        _Pragma("unroll")                                                       \
        for (int nh = 0; nh < 2; nh++) {                                        \
            u32 wh[4];                                                          \
            uint32_t wro = swz((ncol * 32 + nh * 16 + lr) * 128 + koff);        \
            ldsm4(wh, wb + wro);                                                \
            mma_f16(d1[nh * 2],     ah0, wh[0], wh[2]);                         \
            mma_f16(d1[nh * 2 + 1], ah0, wh[1], wh[3]);                         \
            mma_f16(d1[4 + nh * 2],     ah1, wh[0], wh[2]);                     \
            mma_f16(d1[4 + nh * 2 + 1], ah1, wh[1], wh[3]);                     \
        }                                                                       \
    }

__global__ void __launch_bounds__(256, 1) k_proj_h(
    const float* __restrict__ b_out, float* __restrict__ out)
{
    extern __shared__ __align__(128) char dsm[];
    const uint32_t sb = smem_u32(dsm);

    const int tid  = threadIdx.x;
    const int w    = tid >> 5, lane = tid & 31;
    const int lr   = lane & 15, lh = lane >> 4;
    const int q    = lane & 3,  r0 = lane >> 2;
    const int bid  = blockIdx.x;          // 1024
    const int t    = bid >> 1, vh = bid & 1;
    const int mrow = w >> 1, ncol = w & 1;

    const char* pW0 = (const char*)&g_WoTh[vh * 64][0];

    float d1[8][4] = {};
    proj_issue(sb, t, pW0, 0, tid);

    for (int kc = 0; kc < 16; kc++) {
        asm volatile("cp.async.wait_group 0;" ::: "memory");
        __syncthreads();
        if (kc < 15)
            proj_issue(sb + ((kc + 1) & 1) * RBUF_P, t, pW0, kc + 1, tid);
        const uint32_t base = sb + (kc & 1) * RBUF_P;
        CHUNK_MATH_P(base)
    }

#pragma unroll
    for (int mt = 0; mt < 2; mt++) {
#pragma unroll
        for (int rr = 0; rr < 2; rr++) {
            const int b = mrow * 32 + mt * 16 + rr * 8 + r0;
#pragma unroll
            for (int nt = 0; nt < 4; nt++) {
                const int v = vh * 64 + ncol * 32 + nt * 8 + 2 * q;
                float2 bv = *(const float2*)(b_out + v);
                float2 o;
                o.x = d1[mt*4+nt][rr*2+0] + bv.x;
                o.y = d1[mt*4+nt][rr*2+1] + bv.y;
                *(float2*)(out + ((size_t)b * Ssz + t) * Vsz + v) = o;
            }
        }
    }
}

// ------------------------- final state writeback ------------------------------
__global__ void k_states(float* __restrict__ out)
{
    int i = blockIdx.x * blockDim.x + threadIdx.x;
    if (i < Bsz * Hsz) {
        int b = i >> 10, j = i & 1023;
        size_t base = (size_t)Bsz * Ssz * Vsz;
        out[base + 0 * Bsz * Hsz + i] = g_hfin[0][b][j];
        out[base + 1 * Bsz * Hsz + i] = g_hfin[1][b][j];
        out[base + 2 * Bsz * Hsz + i] = g_cfin[0][b][j];
        out[base + 3 * Bsz * Hsz + i] = g_cfin[1][b][j];
    }
}

// ---------------------------------------------------------------------------
extern "C" void kernel_launch(void* const* d_in, const int* in_sizes, int n_in,
                              void* d_out, int out_size)
{
    const int*   x     = (const int*)  d_in[0];
    const float* h_f   = (const float*)d_in[1];
    const float* h_b   = (const float*)d_in[2];
    const float* c_f   = (const float*)d_in[3];
    const float* c_b   = (const float*)d_in[4];
    const float* emb   = (const float*)d_in[5];
    const float* W_f   = (const float*)d_in[6];
    const float* b_f   = (const float*)d_in[7];
    const float* W_b   = (const float*)d_in[8];
    const float* b_b   = (const float*)d_in[9];
    const float* W_out = (const float*)d_in[10];
    const float* b_out = (const float*)d_in[11];
    float* out = (float*)d_out;

    static bool attr_done = false;
    if (!attr_done) {
        cudaFuncSetAttribute(k_recurrent,
                             cudaFuncAttributeMaxDynamicSharedMemorySize, SMEM_REC);
        cudaFuncSetAttribute(k_proj_h,
                             cudaFuncAttributeMaxDynamicSharedMemorySize, SMEM_PROJ);
        attr_done = true;
    }

    k_hinit<<<1024, 256>>>(h_f, h_b);
    k_wprep<<<1024, 256>>>(W_f, W_b);
    k_lut<<<64, 256>>>(emb, W_f, b_f, W_b, b_b);
    k_woutprep<<<1024, 256>>>(W_out);

    k_recurrent<<<NB, 256, SMEM_REC>>>(x, c_f, c_b);

    k_proj_h<<<1024, 256, SMEM_PROJ>>>(b_out, out);
    if (out_size >= (int)((size_t)Bsz * Ssz * Vsz + 4 * Bsz * Hsz))
        k_states<<<512, 256>>>(out);
}